// round 4
// baseline (speedup 1.0000x reference)
#include <cuda_runtime.h>
#include <math_constants.h>

#define NNK      16
#define THREADS  128
#define GSZ      32
#define SUPW     8                     // groups per superblock
#define NMAX     8192
#define NGMAX    (NMAX / GSZ)          // 256
#define NSUP     (NGMAX / SUPW)        // 32
#define PRUNE_EPS 1e-4f

// ---------------- global scratch ------------------------------------------
__device__ double g_sum_minrow;
__device__ double g_sum_mincol;
__device__ double g_sum_dens;

// sorted clouds as float4(x,y,z,|p|^2): [cloud 0=pred,1=true][batch][i]
__device__ float4 g_pts [2][2][NMAX];
__device__ float4 g_bmin[2][2][NGMAX];
__device__ float4 g_bmax[2][2][NGMAX];
__device__ float4 g_smin[2][2][NSUP];
__device__ float4 g_smax[2][2][NSUP];
// sqrt'd knn distances, layout [which][batch][k][i] for coalescing
__device__ float  g_knnd[2][2][NNK][NMAX];

__global__ void init_kernel() {
    g_sum_minrow = 0.0;
    g_sum_mincol = 0.0;
    g_sum_dens   = 0.0;
}

// ---------------- Morton helpers ------------------------------------------
__device__ __forceinline__ unsigned quant6(float v) {
    int q = (int)((v + 8.0f) * 4.0f);
    q = q < 0 ? 0 : (q > 63 ? 63 : q);
    return (unsigned)q;
}
__device__ __forceinline__ unsigned spread3(unsigned v) {
    unsigned r = 0;
#pragma unroll
    for (int b = 0; b < 6; b++) r |= ((v >> b) & 1u) << (3 * b);
    return r;
}

// ---------------- sort kernel: one CTA per (cloud, batch) ------------------
__global__ void __launch_bounds__(1024)
sort_kernel(const float* __restrict__ y_pred, const float* __restrict__ y_true, int N) {
    __shared__ unsigned sk[NMAX];
    int cloud = blockIdx.x >> 1;
    int batch = blockIdx.x & 1;
    const float* src = (cloud ? y_true : y_pred) + (size_t)batch * N * 3;
    int tid = threadIdx.x;

    for (int i = tid; i < NMAX; i += 1024) {
        unsigned key = 0xFFFFFFFFu;
        if (i < N) {
            float x = src[3 * i], y = src[3 * i + 1], z = src[3 * i + 2];
            unsigned code = (spread3(quant6(x)) << 2) | (spread3(quant6(y)) << 1)
                          |  spread3(quant6(z));
            key = (code << 13) | (unsigned)i;
        }
        sk[i] = key;
    }
    __syncthreads();

    for (int k = 2; k <= NMAX; k <<= 1) {
        for (int j = k >> 1; j > 0; j >>= 1) {
            for (int i = tid; i < NMAX; i += 1024) {
                int ixj = i ^ j;
                if (ixj > i) {
                    unsigned a = sk[i], b = sk[ixj];
                    bool up = ((i & k) == 0);
                    if ((a > b) == up) { sk[i] = b; sk[ixj] = a; }
                }
            }
            __syncthreads();
        }
    }

    for (int i = tid; i < N; i += 1024) {
        unsigned idx = sk[i] & 8191u;
        float x = src[3 * idx], y = src[3 * idx + 1], z = src[3 * idx + 2];
        g_pts[cloud][batch][i] = make_float4(x, y, z, x * x + y * y + z * z);
    }
    __syncthreads();

    int NG = N / GSZ;
    for (int g = tid; g < NG; g += 1024) {
        float mnx = CUDART_INF_F, mny = CUDART_INF_F, mnz = CUDART_INF_F;
        float mxx = -CUDART_INF_F, mxy = -CUDART_INF_F, mxz = -CUDART_INF_F;
        for (int t = 0; t < GSZ; t++) {
            float4 p = g_pts[cloud][batch][g * GSZ + t];
            mnx = fminf(mnx, p.x); mxx = fmaxf(mxx, p.x);
            mny = fminf(mny, p.y); mxy = fmaxf(mxy, p.y);
            mnz = fminf(mnz, p.z); mxz = fmaxf(mxz, p.z);
        }
        g_bmin[cloud][batch][g] = make_float4(mnx, mny, mnz, 0.f);
        g_bmax[cloud][batch][g] = make_float4(mxx, mxy, mxz, 0.f);
    }
    __syncthreads();

    int NS = NG / SUPW;
    for (int s = tid; s < NS; s += 1024) {
        float mnx = CUDART_INF_F, mny = CUDART_INF_F, mnz = CUDART_INF_F;
        float mxx = -CUDART_INF_F, mxy = -CUDART_INF_F, mxz = -CUDART_INF_F;
        for (int t = 0; t < SUPW; t++) {
            float4 a = g_bmin[cloud][batch][s * SUPW + t];
            float4 b = g_bmax[cloud][batch][s * SUPW + t];
            mnx = fminf(mnx, a.x); mny = fminf(mny, a.y); mnz = fminf(mnz, a.z);
            mxx = fmaxf(mxx, b.x); mxy = fmaxf(mxy, b.y); mxz = fmaxf(mxz, b.z);
        }
        g_smin[cloud][batch][s] = make_float4(mnx, mny, mnz, 0.f);
        g_smax[cloud][batch][s] = make_float4(mxx, mxy, mxz, 0.f);
    }
}

// ---------------- top-k machinery -----------------------------------------
__device__ __forceinline__ void topk_insert(float (&knn)[NNK], float d2) {
    float x = d2;
#pragma unroll
    for (int k = 0; k < NNK; k++) {
        float lo = fminf(knn[k], x);
        x        = fmaxf(knn[k], x);
        knn[k]   = lo;
    }
}

__device__ __forceinline__ float bbox_dmin2(float4 bn, float4 bx,
                                            float px, float py, float pz) {
    float dx = fmaxf(0.f, fmaxf(bn.x - px, px - bx.x));
    float dy = fmaxf(0.f, fmaxf(bn.y - py, py - bx.y));
    float dz = fmaxf(0.f, fmaxf(bn.z - pz, pz - bx.z));
    return fmaf(dx, dx, fmaf(dy, dy, dz * dz));
}

// ---------------- unified scan kernel --------------------------------------
// task 0: query=true, cand=pred, topk -> g_knnd[0], minrow atomic
// task 1: query=true, cand=true, topk -> g_knnd[1]
// task 2: query=pred, cand=true, min  -> mincol atomic
__global__ void __launch_bounds__(THREADS)
scan_kernel(int N) {
    __shared__ float4 sbmin[NGMAX], sbmax[NGMAX];
    __shared__ float4 ssmin[NSUP],  ssmax[NSUP];
    __shared__ float  redA[THREADS / 32];

    int task  = blockIdx.z;
    int batch = blockIdx.y;
    int i     = blockIdx.x * THREADS + threadIdx.x;
    int NG    = N / GSZ;
    int NS    = NG / SUPW;

    int qcloud = (task == 2) ? 0 : 1;
    int ccloud = (task == 0) ? 0 : 1;

    for (int g = threadIdx.x; g < NG; g += THREADS) {
        sbmin[g] = g_bmin[ccloud][batch][g];
        sbmax[g] = g_bmax[ccloud][batch][g];
    }
    for (int s = threadIdx.x; s < NS; s += THREADS) {
        ssmin[s] = g_smin[ccloud][batch][s];
        ssmax[s] = g_smax[ccloud][batch][s];
    }
    __syncthreads();

    float4 q  = g_pts[qcloud][batch][i];
    float px = q.x, py = q.y, pz = q.z, x2 = q.w;
    float qx = -2.f * px, qy = -2.f * py, qz = -2.f * pz;

    const float4* pts = g_pts[ccloud][batch];
    int gseed = i / GSZ;
    int gs0 = max(0, gseed - 1), gs1 = min(NG - 1, gseed + 1);

    if (task == 2) {
        // ---- min-only scan ----
        float m = CUDART_INF_F;
        for (int g = gs0; g <= gs1; g++) {
            int base = g * GSZ;
#pragma unroll 8
            for (int t = 0; t < GSZ; t++) {
                float4 s  = pts[base + t];
                float  d2 = fmaf(qx, s.x, fmaf(qy, s.y, fmaf(qz, s.z, x2 + s.w)));
                m = fminf(m, d2);
            }
        }
        for (int s = 0; s < NS; s++) {
            float ds = bbox_dmin2(ssmin[s], ssmax[s], px, py, pz);
            if (!__any_sync(0xffffffffu, ds <= m + PRUNE_EPS)) continue;
#pragma unroll
            for (int gg = 0; gg < SUPW; gg++) {
                int g = s * SUPW + gg;
                if (g >= gs0 && g <= gs1) continue;
                float dg = bbox_dmin2(sbmin[g], sbmax[g], px, py, pz);
                if (!__any_sync(0xffffffffu, dg <= m + PRUNE_EPS)) continue;
                int base = g * GSZ;
#pragma unroll 8
                for (int t = 0; t < GSZ; t++) {
                    float4 sp = pts[base + t];
                    float  d2 = fmaf(qx, sp.x, fmaf(qy, sp.y, fmaf(qz, sp.z, x2 + sp.w)));
                    m = fminf(m, d2);
                }
            }
        }
        float mc = sqrtf(fmaxf(m, 0.f));
#pragma unroll
        for (int o = 16; o > 0; o >>= 1) mc += __shfl_down_sync(0xffffffffu, mc, o);
        if ((threadIdx.x & 31) == 0) redA[threadIdx.x >> 5] = mc;
        __syncthreads();
        if (threadIdx.x == 0) {
            float a = 0.f;
#pragma unroll
            for (int w = 0; w < THREADS / 32; w++) a += redA[w];
            atomicAdd(&g_sum_mincol, (double)a);
        }
    } else {
        // ---- top-k scan ----
        float knn[NNK];
#pragma unroll
        for (int k = 0; k < NNK; k++) knn[k] = CUDART_INF_F;
        float kmax = CUDART_INF_F;

        for (int g = gs0; g <= gs1; g++) {
            int base = g * GSZ;
#pragma unroll 8
            for (int t = 0; t < GSZ; t++) {
                float4 sp = pts[base + t];
                float  d2 = fmaf(qx, sp.x, fmaf(qy, sp.y, fmaf(qz, sp.z, x2 + sp.w)));
                if (d2 < kmax) { topk_insert(knn, d2); kmax = knn[NNK - 1]; }
            }
        }
        for (int s = 0; s < NS; s++) {
            float ds = bbox_dmin2(ssmin[s], ssmax[s], px, py, pz);
            if (!__any_sync(0xffffffffu, ds <= kmax + PRUNE_EPS)) continue;
#pragma unroll
            for (int gg = 0; gg < SUPW; gg++) {
                int g = s * SUPW + gg;
                if (g >= gs0 && g <= gs1) continue;
                float dg = bbox_dmin2(sbmin[g], sbmax[g], px, py, pz);
                if (!__any_sync(0xffffffffu, dg <= kmax + PRUNE_EPS)) continue;
                int base = g * GSZ;
#pragma unroll 8
                for (int t = 0; t < GSZ; t++) {
                    float4 sp = pts[base + t];
                    float  d2 = fmaf(qx, sp.x, fmaf(qy, sp.y, fmaf(qz, sp.z, x2 + sp.w)));
                    if (d2 < kmax) { topk_insert(knn, d2); kmax = knn[NNK - 1]; }
                }
            }
        }

        // write sqrt'd list (coalesced per k)
#pragma unroll
        for (int k = 0; k < NNK; k++)
            g_knnd[task][batch][k][i] = sqrtf(fmaxf(knn[k], 0.f));

        if (task == 0) {
            float minr = sqrtf(fmaxf(knn[0], 0.f));
#pragma unroll
            for (int o = 16; o > 0; o >>= 1) minr += __shfl_down_sync(0xffffffffu, minr, o);
            if ((threadIdx.x & 31) == 0) redA[threadIdx.x >> 5] = minr;
            __syncthreads();
            if (threadIdx.x == 0) {
                float a = 0.f;
#pragma unroll
                for (int w = 0; w < THREADS / 32; w++) a += redA[w];
                atomicAdd(&g_sum_minrow, (double)a);
            }
        }
    }
}

// ---------------- combine: density loss ------------------------------------
__global__ void __launch_bounds__(256)
combine_kernel(int N) {
    __shared__ float red[8];
    int batch = blockIdx.y;
    int i = blockIdx.x * 256 + threadIdx.x;

    float dens = 0.f;
#pragma unroll
    for (int k = 0; k < NNK; k++)
        dens += fabsf(g_knnd[0][batch][k][i] - g_knnd[1][batch][k][i]);

#pragma unroll
    for (int o = 16; o > 0; o >>= 1) dens += __shfl_down_sync(0xffffffffu, dens, o);
    if ((threadIdx.x & 31) == 0) red[threadIdx.x >> 5] = dens;
    __syncthreads();
    if (threadIdx.x == 0) {
        float a = 0.f;
#pragma unroll
        for (int w = 0; w < 8; w++) a += red[w];
        atomicAdd(&g_sum_dens, (double)a);
    }
}

__global__ void finalize_kernel(float* __restrict__ out, int BN) {
    double inv   = 1.0 / (double)BN;
    double shape = 0.5 * (g_sum_minrow * inv + g_sum_mincol * inv);
    double dens  = g_sum_dens / ((double)BN * (double)NNK);
    out[0] = (float)(shape + dens);
    out[1] = (float)shape;
    out[2] = (float)dens;
}

extern "C" void kernel_launch(void* const* d_in, const int* in_sizes, int n_in,
                              void* d_out, int out_size) {
    const float* y_pred = (const float*)d_in[0];
    const float* y_true = (const float*)d_in[1];
    const int B = 2, C = 3;
    int N = in_sizes[0] / (B * C);

    init_kernel<<<1, 1>>>();
    sort_kernel<<<4, 1024>>>(y_pred, y_true, N);
    dim3 grid(N / THREADS, B, 3);
    scan_kernel<<<grid, THREADS>>>(N);
    dim3 cgrid(N / 256, B);
    combine_kernel<<<cgrid, 256>>>(N);
    finalize_kernel<<<1, 1>>>((float*)d_out, B * N);
}